// round 1
// baseline (speedup 1.0000x reference)
#include <cuda_runtime.h>

#define S 1024
#define G 10
#define F 5
#define B 8
#define C 3
#define KW (2*F+1)

// Scratch: smoothed+clipped offset field, [batch][{x,y}][G][G]
__device__ float g_sm[B][2][G][G];

__global__ void smooth_kernel(const float* __restrict__ ox,
                              const float* __restrict__ oy,
                              const float* __restrict__ w,
                              const void* __restrict__ mm_p) {
    int idx = blockIdx.x * blockDim.x + threadIdx.x;
    if (idx >= B * 2 * G * G) return;
    int j  = idx % G;
    int i  = (idx / G) % G;
    int ch = (idx / (G * G)) % 2;
    int b  = idx / (2 * G * G);

    // max_move may arrive as int32 or float32 — decode robustly.
    int raw = *(const int*)mm_p;
    float mmv = (raw >= 0 && raw < 1000000) ? (float)raw : __int_as_float(raw);
    float max_offset = 2.0f * mmv / (float)S;

    const float* o = (ch == 0 ? ox : oy) + b * G * G;
    float acc = 0.0f;
    #pragma unroll
    for (int u = 0; u < KW; u++) {
        int ii = min(max(i + u - F, 0), G - 1);
        #pragma unroll
        for (int v = 0; v < KW; v++) {
            int jj = min(max(j + v - F, 0), G - 1);
            acc = fmaf(w[u * KW + v], o[ii * G + jj], acc);
        }
    }
    acc *= max_offset;
    acc = fminf(fmaxf(acc, -max_offset), max_offset);
    g_sm[b][ch][i][j] = acc;
}

__global__ __launch_bounds__(256) void deform_kernel(const float* __restrict__ xin,
                                                     float* __restrict__ out) {
    __shared__ float sgx[G * G];
    __shared__ float sgy[G * G];
    __shared__ float rowx[G];
    __shared__ float rowy[G];

    const int b   = blockIdx.z;
    const int y   = blockIdx.y;
    const int x   = blockIdx.x * blockDim.x + threadIdx.x;
    const int tid = threadIdx.x;

    if (tid < G * G) {
        sgx[tid] = g_sm[b][0][0][tid];
        sgy[tid] = g_sm[b][1][0][tid];
    }
    __syncthreads();

    if (tid < G) {
        // Row (y-direction) interpolation of the coarse field — shared by whole row.
        float src = fmaxf((y + 0.5f) * ((float)G / (float)S) - 0.5f, 0.0f);
        int i0 = min((int)floorf(src), G - 1);
        int i1 = min(i0 + 1, G - 1);
        float wr = src - (float)i0;
        rowx[tid] = sgx[i0 * G + tid] * (1.0f - wr) + sgx[i1 * G + tid] * wr;
        rowy[tid] = sgy[i0 * G + tid] * (1.0f - wr) + sgy[i1 * G + tid] * wr;
    }
    __syncthreads();

    // Column (x-direction) interpolation
    float srcx = fmaxf((x + 0.5f) * ((float)G / (float)S) - 0.5f, 0.0f);
    int j0 = min((int)floorf(srcx), G - 1);
    int j1 = min(j0 + 1, G - 1);
    float wc = srcx - (float)j0;
    float gx = rowx[j0] * (1.0f - wc) + rowx[j1] * wc;
    float gy = rowy[j0] * (1.0f - wc) + rowy[j1] * wc;

    // Identity grid (match reference op order: lin = i/(S-1); P = lin*2-1)
    float Px = ((float)x / (float)(S - 1)) * 2.0f - 1.0f;
    float Py = ((float)y / (float)(S - 1)) * 2.0f - 1.0f;

    float g0 = fminf(fmaxf(gx + Px, -1.0f), 1.0f);
    float g1 = fminf(fmaxf(gy + Py, -1.0f), 1.0f);

    // grid_sample coordinates
    float ix = ((g0 + 1.0f) * (float)S - 1.0f) * 0.5f;
    float iy = ((g1 + 1.0f) * (float)S - 1.0f) * 0.5f;

    int x0 = (int)floorf(ix);
    int y0 = (int)floorf(iy);
    int x1 = x0 + 1;
    int y1 = y0 + 1;
    float wx = ix - (float)x0;
    float wy = iy - (float)y0;

    // Zero-padding masks folded into weights
    float mx0 = (x0 >= 0 && x0 < S) ? 1.0f : 0.0f;
    float mx1 = (x1 >= 0 && x1 < S) ? 1.0f : 0.0f;
    float my0 = (y0 >= 0 && y0 < S) ? 1.0f : 0.0f;
    float my1 = (y1 >= 0 && y1 < S) ? 1.0f : 0.0f;

    float w00 = (1.0f - wy) * (1.0f - wx) * my0 * mx0;
    float w01 = (1.0f - wy) * wx          * my0 * mx1;
    float w10 = wy          * (1.0f - wx) * my1 * mx0;
    float w11 = wy          * wx          * my1 * mx1;

    int cx0 = min(max(x0, 0), S - 1);
    int cx1 = min(max(x1, 0), S - 1);
    int cy0 = min(max(y0, 0), S - 1);
    int cy1 = min(max(y1, 0), S - 1);

    const size_t r0 = (size_t)cy0 * S;
    const size_t r1 = (size_t)cy1 * S;

    #pragma unroll
    for (int c = 0; c < C; c++) {
        const float* img = xin + ((size_t)(b * C + c)) * S * S;
        float v = img[r0 + cx0] * w00
                + img[r0 + cx1] * w01
                + img[r1 + cx0] * w10
                + img[r1 + cx1] * w11;
        out[(((size_t)(b * C + c)) * S + y) * S + x] = v;
    }
}

extern "C" void kernel_launch(void* const* d_in, const int* in_sizes, int n_in,
                              void* d_out, int out_size) {
    const float* x  = (const float*)d_in[0];
    const float* ox = (const float*)d_in[1];
    const float* oy = (const float*)d_in[2];
    const float* w  = (const float*)d_in[3];
    const void*  mm = d_in[4];

    smooth_kernel<<<(B * 2 * G * G + 255) / 256, 256>>>(ox, oy, w, mm);

    dim3 grid(S / 256, S, B);
    deform_kernel<<<grid, 256>>>(x, (float*)d_out);
}

// round 6
// speedup vs baseline: 1.0088x; 1.0088x over previous
#include <cuda_runtime.h>

#define S 1024
#define G 10
#define F 5
#define B 8
#define C 3
#define KW (2*F+1)
#define YCHUNKS 8
#define YROWS (S / YCHUNKS)

// Scratch: per-row y-interpolated coarse field: (gx, gy) for each (b, y, j)
__device__ float2 g_rows[B][S][G];

// ---------------------------------------------------------------------------
// Prep: 11x11 edge-padded conv on 10x10 offsets, clip, then expand along y
// into per-row interpolated fields.  grid = (B, YCHUNKS), 256 threads.
// ---------------------------------------------------------------------------
__global__ __launch_bounds__(256) void prep_kernel(const float* __restrict__ ox,
                                                   const float* __restrict__ oy,
                                                   const float* __restrict__ w,
                                                   const void* __restrict__ mm_p) {
    __shared__ float sc[2][G][G];

    const int b     = blockIdx.x;
    const int chunk = blockIdx.y;
    const int tid   = threadIdx.x;

    if (tid < 2 * G * G) {
        int ch  = tid / (G * G);
        int rem = tid % (G * G);
        int i   = rem / G;
        int j   = rem % G;

        // max_move may arrive as int32 or float32 — decode robustly.
        int raw = *(const int*)mm_p;
        float mmv = (raw >= 0 && raw < 1000000) ? (float)raw : __int_as_float(raw);
        float max_offset = 2.0f * mmv / (float)S;

        const float* o = (ch ? oy : ox) + b * G * G;
        float acc = 0.0f;
        for (int u = 0; u < KW; u++) {
            int ii = min(max(i + u - F, 0), G - 1);
            #pragma unroll
            for (int v = 0; v < KW; v++) {
                int jj = min(max(j + v - F, 0), G - 1);
                acc = fmaf(w[u * KW + v], o[ii * G + jj], acc);
            }
        }
        acc *= max_offset;
        acc = fminf(fmaxf(acc, -max_offset), max_offset);
        sc[ch][i][j] = acc;
    }
    __syncthreads();

    for (int k = tid; k < YROWS * G; k += 256) {
        int yl = k / G;
        int j  = k % G;
        int y  = chunk * YROWS + yl;

        float src = fmaxf((y + 0.5f) * ((float)G / (float)S) - 0.5f, 0.0f);
        int i0 = min((int)src, G - 1);           // src >= 0 -> trunc == floor
        int i1 = min(i0 + 1, G - 1);
        float wr = src - (float)i0;

        float gx = sc[0][i0][j] * (1.0f - wr) + sc[0][i1][j] * wr;
        float gy = sc[1][i0][j] * (1.0f - wr) + sc[1][i1][j] * wr;
        g_rows[b][y][j] = make_float2(gx, gy);
    }
}

// ---------------------------------------------------------------------------
// Deform: one block per (row, batch); 256 threads x 4 pixels; float4 stores.
// ---------------------------------------------------------------------------
__global__ __launch_bounds__(256, 4) void deform_kernel(const float* __restrict__ xin,
                                                        float* __restrict__ out) {
    __shared__ float2 srow[G];

    const int b   = blockIdx.y;
    const int y   = blockIdx.x;
    const int tid = threadIdx.x;

    if (tid < G) srow[tid] = g_rows[b][y][tid];
    __syncthreads();

    const int xbase = tid * 4;
    const float* xb = xin + (size_t)b * C * S * S;
    const float Py  = fmaf((float)y, 2.0f / (float)(S - 1), -1.0f);

    float4 acc0, acc1, acc2;
    float* a0 = (float*)&acc0;
    float* a1 = (float*)&acc1;
    float* a2 = (float*)&acc2;

    #pragma unroll
    for (int p = 0; p < 4; p++) {
        const int x = xbase + p;

        // Column interp of coarse field
        float srcx = fmaxf((x + 0.5f) * ((float)G / (float)S) - 0.5f, 0.0f);
        int j0 = min((int)srcx, G - 1);
        int j1 = min(j0 + 1, G - 1);
        float wc = srcx - (float)j0;
        float2 fa = srow[j0];
        float2 fb = srow[j1];
        float gx = fa.x * (1.0f - wc) + fb.x * wc;
        float gy = fa.y * (1.0f - wc) + fb.y * wc;

        // Identity grid + clip
        float Px = fmaf((float)x, 2.0f / (float)(S - 1), -1.0f);
        float g0 = fminf(fmaxf(gx + Px, -1.0f), 1.0f);
        float g1 = fminf(fmaxf(gy + Py, -1.0f), 1.0f);

        // Sample coords: ((g+1)*S - 1) / 2 == g*512 + 511.5
        float ix = fmaf(g0, 512.0f, 511.5f);
        float iy = fmaf(g1, 512.0f, 511.5f);

        float fx = floorf(ix);
        float fy = floorf(iy);
        int x0 = (int)fx;
        int y0 = (int)fy;
        float wx = ix - fx;
        float wy = iy - fy;
        int x1 = x0 + 1;
        int y1 = y0 + 1;

        // ix in [-0.5, 1023.5] -> x0 in [-1,1023], x1 in [0,1024]:
        // only the low side of x0 and high side of x1 can be OOB.
        float wxa = (x0 >= 0)     ? (1.0f - wx) : 0.0f;
        float wxb = (x1 <= S - 1) ? wx          : 0.0f;
        float wya = (y0 >= 0)     ? (1.0f - wy) : 0.0f;
        float wyb = (y1 <= S - 1) ? wy          : 0.0f;

        int cx0 = max(x0, 0);
        int cx1 = min(x1, S - 1);
        int cy0 = max(y0, 0);
        int cy1 = min(y1, S - 1);

        float w00 = wya * wxa;
        float w01 = wya * wxb;
        float w10 = wyb * wxa;
        float w11 = wyb * wxb;

        int o00 = cy0 * S + cx0;
        int o01 = cy0 * S + cx1;
        int o10 = cy1 * S + cx0;
        int o11 = cy1 * S + cx1;

        {
            const float* img = xb;
            a0[p] = img[o00] * w00 + img[o01] * w01 + img[o10] * w10 + img[o11] * w11;
        }
        {
            const float* img = xb + S * S;
            a1[p] = img[o00] * w00 + img[o01] * w01 + img[o10] * w10 + img[o11] * w11;
        }
        {
            const float* img = xb + 2 * S * S;
            a2[p] = img[o00] * w00 + img[o01] * w01 + img[o10] * w10 + img[o11] * w11;
        }
    }

    float* ob = out + (((size_t)(b * C) * S) + y) * S + xbase;
    *(float4*)(ob)             = acc0;
    *(float4*)(ob + S * S)     = acc1;
    *(float4*)(ob + 2 * S * S) = acc2;
}

extern "C" void kernel_launch(void* const* d_in, const int* in_sizes, int n_in,
                              void* d_out, int out_size) {
    const float* x  = (const float*)d_in[0];
    const float* ox = (const float*)d_in[1];
    const float* oy = (const float*)d_in[2];
    const float* w  = (const float*)d_in[3];
    const void*  mm = d_in[4];

    prep_kernel<<<dim3(B, YCHUNKS), 256>>>(ox, oy, w, mm);

    dim3 grid(S, B);
    deform_kernel<<<grid, 256>>>(x, (float*)d_out);
}